// round 5
// baseline (speedup 1.0000x reference)
#include <cuda_runtime.h>
#include <math.h>

#define BATCH 64
#define NPART 512
#define SPLIT 8
#define BLK   256
#define EPT   (NPART / BLK)      // 2 elements per thread in load phase
#define NW    (BLK / 32)         // 8 warps
#define NGRP  (NW * EPT)         // 16 (warp, e) groups per side
#define GRID  (BATCH * SPLIT)    // 512 CTAs

// Scratch (no allocation allowed).
// g_part[b][s][0..3] = sum_xy per class (1..4), [4..7] = sum_yx per class.
__device__ float g_part[BATCH][SPLIT][8];
__device__ float g_batch[BATCH][2];   // per-batch (nz, zz)
__device__ int   g_btick[BATCH];      // per-batch arrival counters (reset in-kernel)
__device__ int   g_ticket;            // global arrival counter (reset in-kernel)

__global__ __launch_bounds__(BLK)
void chamfer_fused(const float4* __restrict__ target,
                   const float4* __restrict__ reco,
                   const int*    __restrict__ in_pid,
                   const int*    __restrict__ out_pid,
                   float* __restrict__ out, int out_size)
{
    __shared__ float4 sT[NPART], sR[NPART];      // class-compacted particles
    __shared__ float  sQT[NPART], sQR[NPART];    // 0.5*|p|^2 (compacted)
    __shared__ float  sNT[NPART], sNR[NPART];    // |p| (compacted)
    __shared__ int    bX[NGRP][5], bY[NGRP][5];  // group counts -> group prefixes
    __shared__ int    totX[5], totY[5];
    __shared__ int    offX[6], offY[6];
    __shared__ float  accA[5], accB[5];
    __shared__ float  mNT[5], mNR[5];            // local per-class norm sums
    __shared__ float  pp[SPLIT][8];              // gathered split partials (batch-last)
    __shared__ float  sBnz[BATCH], sBzz[BATCH];  // final gather (global-last)
    __shared__ int    fl1, fl2;

    const int b    = blockIdx.x / SPLIT;
    const int s    = blockIdx.x % SPLIT;
    const int tid  = threadIdx.x;
    const int w    = tid >> 5;
    const int lane = tid & 31;
    const unsigned lt = (1u << lane) - 1u;

    if (tid < 5) { accA[tid] = 0.f; accB[tid] = 0.f; }
    if (tid < NGRP * 5) { (&bX[0][0])[tid] = 0; (&bY[0][0])[tid] = 0; }
    __syncthreads();

    const float4* Tb  = target  + b * NPART;
    const float4* Rb  = reco    + b * NPART;
    const int*    IPb = in_pid  + b * NPART;
    const int*    OPb = out_pid + b * NPART;

    // ---- Load + atomic-free binning via match_any + lane rank ----
    float4 tv[EPT], rv[EPT];
    int    tp[EPT], rp[EPT], rkX[EPT], rkY[EPT];
#pragma unroll
    for (int e = 0; e < EPT; e++) {
        const int i = e * BLK + tid;
        tv[e] = Tb[i]; rv[e] = Rb[i];
        tp[e] = IPb[i]; rp[e] = OPb[i];
        const unsigned mX = __match_any_sync(0xffffffffu, tp[e]);
        const unsigned mY = __match_any_sync(0xffffffffu, rp[e]);
        rkX[e] = __popc(mX & lt);
        rkY[e] = __popc(mY & lt);
        const int g = w * EPT + e;
        if (rkX[e] == 0) bX[g][tp[e]] = __popc(mX);
        if (rkY[e] == 0) bY[g][rp[e]] = __popc(mY);
    }
    __syncthreads();

    // ---- Exclusive prefix over the 16 groups, per class: register-resident ----
    if (tid < 10) {
        const int side = tid / 5, q = tid % 5;
        int (*bb)[5] = side ? bY : bX;
        int v[NGRP];
#pragma unroll
        for (int g = 0; g < NGRP; g++) v[g] = bb[g][q];
        int run = 0;
#pragma unroll
        for (int g = 0; g < NGRP; g++) { const int c = v[g]; bb[g][q] = run; run += c; }
        if (side) totY[q] = run; else totX[q] = run;
    }
    __syncthreads();
    if (tid == 0) { int a = 0; for (int q = 0; q < 5; q++) { offX[q] = a; a += totX[q]; } offX[5] = a; }
    if (tid == 1) { int a = 0; for (int q = 0; q < 5; q++) { offY[q] = a; a += totY[q]; } offY[5] = a; }
    __syncthreads();

    // ---- Deterministic scatter (no atomics): particle, half-sq-norm, norm ----
#pragma unroll
    for (int e = 0; e < EPT; e++) {
        const int g  = w * EPT + e;
        const int ix = offX[tp[e]] + bX[g][tp[e]] + rkX[e];
        const int iy = offY[rp[e]] + bY[g][rp[e]] + rkY[e];
        const float4 t = tv[e], r = rv[e];
        const float tq = t.x*t.x + t.y*t.y + t.z*t.z + t.w*t.w;
        const float rq = r.x*r.x + r.y*r.y + r.z*r.z + r.w*r.w;
        sT[ix] = t;  sQT[ix] = 0.5f * tq;  sNT[ix] = sqrtf(tq);
        sR[iy] = r;  sQR[iy] = 0.5f * rq;  sNR[iy] = sqrtf(rq);
    }
    __syncthreads();

    // ---- Local metadata: class-contiguous norm segment sums (all CTAs) ----
    for (int seg = w; seg < 9; seg += NW) {
        int lo, hi; const float* arr;
        if (seg < 4) { arr = sNT; lo = offX[seg + 1]; hi = offX[seg + 2]; }
        else         { arr = sNR; lo = offY[seg - 4]; hi = offY[seg - 3]; }
        float sum = 0.f;
        for (int j = lo + lane; j < hi; j += 32) sum += arr[j];
#pragma unroll
        for (int o = 16; o; o >>= 1) sum += __shfl_down_sync(0xffffffffu, sum, o);
        if (lane == 0) {
            if (seg < 4)       mNT[seg + 1] = sum;   // |t| sums, class 1..4
            else if (seg == 4) mNR[0]       = sum;   // |r| sum, class 0
            else               mNR[seg - 4] = sum;   // |r| sums, class 1..4
        }
    }

    // ---- Main work: each item handled by a THREAD PAIR (halved j-chain) ----
    // min_j |x-y_j|^2 = |x|^2 + 2*min_j(h_j - x.y_j),  h_j = 0.5|y_j|^2
    const int nA = NPART - offX[1];
    const int nB = NPART - offY[1];
    const int gm   = s * BLK + tid;      // SPLIT*BLK = 2048 threads per batch
    const int m    = gm >> 1;            // item index (<= 1024 items)
    const int half = gm & 1;

    float ms = INFINITY;
    bool  doit = false, passA = false;
    int   q = 1;
    float xsq = 0.f;

    if (m < nA + nB) {
        passA = (m < nA);
        int k = passA ? (offX[1] + m) : (offY[1] + (m - nA));
        const int* off_self  = passA ? offX : offY;
        const int* off_other = passA ? offY : offX;

        while (k >= off_self[q + 1]) q++;

        const int jb = off_other[q], je = off_other[q + 1];
        if (jb != je) {
            doit = true;
            const float4  x     = passA ? sT[k]  : sR[k];
            xsq                 = 2.f * (passA ? sQT[k] : sQR[k]);
            const float4* other = passA ? sR  : sT;
            const float*  hoth  = passA ? sQR : sQT;
            const float nx = -x.x, ny = -x.y, nz = -x.z, nw = -x.w;
            for (int j = jb + half; j < je; j += 2) {
                const float4 y = other[j];
                const float sc = fmaf(nx, y.x, fmaf(ny, y.y, fmaf(nz, y.z, fmaf(nw, y.w, hoth[j]))));
                ms = fminf(ms, sc);
            }
        }
    }
    // combine pair halves (partner is lane^1, same warp)
    ms = fminf(ms, __shfl_xor_sync(0xffffffffu, ms, 1));
    if (doit && half == 0) {
        const float d2 = fmaxf(fmaf(2.f, ms, xsq), 0.f);
        atomicAdd(passA ? &accA[q] : &accB[q], sqrtf(d2));
    }
    __syncthreads();

    if (tid < 4) {
        g_part[b][s][tid]     = accA[tid + 1];
        g_part[b][s][4 + tid] = accB[tid + 1];
    }

    // ---- Level 1: per-batch completion (64 spread counters) ----
    __threadfence();
    __syncthreads();
    if (tid == 0) fl1 = (atomicAdd(&g_btick[b], 1) == SPLIT - 1);
    __syncthreads();
    if (!fl1) return;

    // batch-last CTA: gather all splits' partials, compute per-batch scalars
    __threadfence();                      // acquire other splits' g_part
    if (tid < SPLIT * 8) {                // scalar copies: alignment-safe
        const int ss = tid >> 3, qq = tid & 7;
        pp[ss][qq] = g_part[b][ss][qq];
    }
    __syncthreads();
    if (tid == 0) {
        float nzsum = 0.f;
#pragma unroll
        for (int qq = 0; qq < 4; qq++) {
            const float cx = (float)(offX[qq + 2] - offX[qq + 1]);
            const float cy = (float)(offY[qq + 2] - offY[qq + 1]);
            float sxy = 0.f, syx = 0.f;
#pragma unroll
            for (int ss = 0; ss < SPLIT; ss++) { sxy += pp[ss][qq]; syx += pp[ss][4 + qq]; }
            float per;
            if (cy == 0.f)      per = mNT[qq + 1] / fmaxf(1.f, cx);
            else if (cx == 0.f) per = mNR[qq + 1] / fmaxf(1.f, cy);
            else                per = 0.5f * (sxy / fmaxf(1.f, cy) + syx / fmaxf(1.f, cx));
            nzsum += per;
        }
        g_batch[b][0] = nzsum;
        g_batch[b][1] = mNR[0] / fmaxf(1.f, (float)(offY[1] - offY[0]));
        g_btick[b] = 0;                   // reset for next graph replay
    }

    // ---- Level 2: global completion (64 contenders) ----
    __syncthreads();
    __threadfence();
    if (tid == 0) fl2 = (atomicAdd(&g_ticket, 1) == BATCH - 1);
    __syncthreads();
    if (!fl2) return;

    __threadfence();                      // acquire all g_batch
    if (tid < BATCH) {
        sBnz[tid] = g_batch[tid][0];
        sBzz[tid] = g_batch[tid][1];
    }
    __syncthreads();
    if (tid == 0) {
        float a = 0.f, c = 0.f;
        for (int i = 0; i < BATCH; i++) { a += sBnz[i]; c += sBzz[i]; }
        out[0] = a / (float)BATCH;
        if (out_size > 1) out[1] = c / (float)BATCH;
        g_ticket = 0;                     // reset for next graph replay
    }
}

extern "C" void kernel_launch(void* const* d_in, const int* in_sizes, int n_in,
                              void* d_out, int out_size)
{
    const float4* target = (const float4*)d_in[0];
    const float4* reco   = (const float4*)d_in[1];
    const int*    ipid   = (const int*)d_in[2];
    const int*    opid   = (const int*)d_in[3];
    float*        out    = (float*)d_out;
    (void)in_sizes; (void)n_in;

    chamfer_fused<<<GRID, BLK>>>(target, reco, ipid, opid, out, out_size);
}

// round 6
// speedup vs baseline: 1.0325x; 1.0325x over previous
#include <cuda_runtime.h>
#include <math.h>

#define BATCH 64
#define NPART 512
#define SPLIT 2
#define BLK   512
#define NW    (BLK / 32)         // 16 warps; each warp is one binning group
#define NGRP  NW                 // 16 groups per side (EPT = 1)
#define GRID  (BATCH * SPLIT)    // 128 CTAs

// Scratch (no allocation allowed).
// g_part[b][s][0..3] = sum_xy per class (1..4), [4..7] = sum_yx per class.
__device__ float g_part[BATCH][SPLIT][8];
__device__ float g_batch[BATCH][2];   // per-batch (nz, zz)
__device__ int   g_btick[BATCH];      // per-batch arrival counters (reset in-kernel)
__device__ int   g_ticket;            // global arrival counter (reset in-kernel)

__global__ __launch_bounds__(BLK)
void chamfer_fused(const float4* __restrict__ target,
                   const float4* __restrict__ reco,
                   const int*    __restrict__ in_pid,
                   const int*    __restrict__ out_pid,
                   float* __restrict__ out, int out_size)
{
    __shared__ float4 sT[NPART], sR[NPART];      // class-compacted particles
    __shared__ float  sQT[NPART], sQR[NPART];    // 0.5*|p|^2 (compacted)
    __shared__ int    bX[NGRP][5], bY[NGRP][5];  // group counts -> group prefixes
    __shared__ int    totX[5], totY[5];
    __shared__ int    offX[6], offY[6];
    __shared__ float  accA[5], accB[5];
    __shared__ float  mNT[5], mNR[5];            // per-class norm sums (batch-last only)
    __shared__ float  pp[SPLIT][8];              // gathered split partials (batch-last)
    __shared__ float  sBnz[BATCH], sBzz[BATCH];  // final gather (global-last)
    __shared__ int    fl1, fl2;

    const int b    = blockIdx.x / SPLIT;
    const int s    = blockIdx.x % SPLIT;
    const int tid  = threadIdx.x;
    const int w    = tid >> 5;
    const int lane = tid & 31;
    const unsigned lt = (1u << lane) - 1u;

    if (tid < 5) { accA[tid] = 0.f; accB[tid] = 0.f; }
    if (tid < NGRP * 5) { (&bX[0][0])[tid] = 0; (&bY[0][0])[tid] = 0; }
    __syncthreads();

    const float4* Tb  = target  + b * NPART;
    const float4* Rb  = reco    + b * NPART;
    const int*    IPb = in_pid  + b * NPART;
    const int*    OPb = out_pid + b * NPART;

    // ---- Load (1 target + 1 reco per thread) + atomic-free binning ----
    const float4 tv = Tb[tid];
    const float4 rv = Rb[tid];
    const int    tp = IPb[tid];
    const int    rp = OPb[tid];
    const unsigned mX = __match_any_sync(0xffffffffu, tp);
    const unsigned mY = __match_any_sync(0xffffffffu, rp);
    const int rkX = __popc(mX & lt);
    const int rkY = __popc(mY & lt);
    if (rkX == 0) bX[w][tp] = __popc(mX);
    if (rkY == 0) bY[w][rp] = __popc(mY);
    __syncthreads();

    // ---- Exclusive prefix over the 16 groups, per class: register-resident ----
    if (tid < 10) {
        const int side = tid / 5, q = tid % 5;
        int (*bb)[5] = side ? bY : bX;
        int v[NGRP];
#pragma unroll
        for (int g = 0; g < NGRP; g++) v[g] = bb[g][q];
        int run = 0;
#pragma unroll
        for (int g = 0; g < NGRP; g++) { const int c = v[g]; bb[g][q] = run; run += c; }
        if (side) totY[q] = run; else totX[q] = run;
    }
    __syncthreads();
    if (tid == 0) { int a = 0; for (int q = 0; q < 5; q++) { offX[q] = a; a += totX[q]; } offX[5] = a; }
    if (tid == 1) { int a = 0; for (int q = 0; q < 5; q++) { offY[q] = a; a += totY[q]; } offY[5] = a; }
    __syncthreads();

    // ---- Deterministic scatter (no atomics): particle + half-sq-norm ----
    {
        const int ix = offX[tp] + bX[w][tp] + rkX;
        const int iy = offY[rp] + bY[w][rp] + rkY;
        sT[ix] = tv;  sQT[ix] = 0.5f * (tv.x*tv.x + tv.y*tv.y + tv.z*tv.z + tv.w*tv.w);
        sR[iy] = rv;  sQR[iy] = 0.5f * (rv.x*rv.x + rv.y*rv.y + rv.z*rv.z + rv.w*rv.w);
    }
    __syncthreads();

    // ---- Main work: one item per thread (classes 1..4 only) ----
    // min_j |x-y_j|^2 = |x|^2 + 2*min_j(h_j - x.y_j),  h_j = 0.5|y_j|^2
    const int nA = NPART - offX[1];
    const int nB = NPART - offY[1];
    const int m  = s * BLK + tid;          // SPLIT*BLK = 1024 >= nA+nB

    if (m < nA + nB) {
        const bool passA = (m < nA);
        int k = passA ? (offX[1] + m) : (offY[1] + (m - nA));
        const int* off_self  = passA ? offX : offY;
        const int* off_other = passA ? offY : offX;

        int q = 1;
        while (k >= off_self[q + 1]) q++;

        const int jb = off_other[q], je = off_other[q + 1];
        if (jb != je) {
            const float4  x     = passA ? sT[k]  : sR[k];
            const float   xsq   = 2.f * (passA ? sQT[k] : sQR[k]);
            const float4* other = passA ? sR  : sT;
            const float*  hoth  = passA ? sQR : sQT;
            const float nx = -x.x, ny = -x.y, nz = -x.z, nw = -x.w;

            float ms0 = INFINITY, ms1 = INFINITY;
            int j = jb;
            if ((je - jb) & 1) {
                const float4 y = other[j];
                ms0 = fmaf(nx, y.x, fmaf(ny, y.y, fmaf(nz, y.z, fmaf(nw, y.w, hoth[j]))));
                j++;
            }
#pragma unroll 4
            for (; j < je; j += 2) {
                const float4 y0 = other[j];
                const float4 y1 = other[j + 1];
                const float s0 = fmaf(nx, y0.x, fmaf(ny, y0.y, fmaf(nz, y0.z, fmaf(nw, y0.w, hoth[j]))));
                const float s1 = fmaf(nx, y1.x, fmaf(ny, y1.y, fmaf(nz, y1.z, fmaf(nw, y1.w, hoth[j + 1]))));
                ms0 = fminf(ms0, s0);
                ms1 = fminf(ms1, s1);
            }
            const float ms = fminf(ms0, ms1);
            const float d2 = fmaxf(fmaf(2.f, ms, xsq), 0.f);
            atomicAdd(passA ? &accA[q] : &accB[q], sqrtf(d2));
        }
    }
    __syncthreads();

    if (tid < 4) {
        g_part[b][s][tid]     = accA[tid + 1];
        g_part[b][s][4 + tid] = accB[tid + 1];
    }

    // ---- Level 1: per-batch completion (64 spread counters) ----
    __threadfence();
    __syncthreads();
    if (tid == 0) fl1 = (atomicAdd(&g_btick[b], 1) == SPLIT - 1);
    __syncthreads();
    if (!fl1) return;

    // ---- Batch-last CTA only: metadata (per-class norm sums) + combine ----
    // |p| = sqrt(2 * sQ)
    for (int seg = w; seg < 9; seg += NW) {
        int lo, hi; const float* qq;
        if (seg < 4) { qq = sQT; lo = offX[seg + 1]; hi = offX[seg + 2]; }
        else         { qq = sQR; lo = offY[seg - 4]; hi = offY[seg - 3]; }
        float sum = 0.f;
        for (int j = lo + lane; j < hi; j += 32) sum += sqrtf(2.f * qq[j]);
#pragma unroll
        for (int o = 16; o; o >>= 1) sum += __shfl_down_sync(0xffffffffu, sum, o);
        if (lane == 0) {
            if (seg < 4)       mNT[seg + 1] = sum;   // |t| sums, class 1..4
            else if (seg == 4) mNR[0]       = sum;   // |r| sum, class 0
            else               mNR[seg - 4] = sum;   // |r| sums, class 1..4
        }
    }
    __threadfence();                      // acquire other splits' g_part
    if (tid < SPLIT * 8) {                // scalar copies: alignment-safe
        const int ss = tid >> 3, qq = tid & 7;
        pp[ss][qq] = g_part[b][ss][qq];
    }
    __syncthreads();
    if (tid == 0) {
        float nzsum = 0.f;
#pragma unroll
        for (int qq = 0; qq < 4; qq++) {
            const float cx = (float)(offX[qq + 2] - offX[qq + 1]);
            const float cy = (float)(offY[qq + 2] - offY[qq + 1]);
            float sxy = 0.f, syx = 0.f;
#pragma unroll
            for (int ss = 0; ss < SPLIT; ss++) { sxy += pp[ss][qq]; syx += pp[ss][4 + qq]; }
            float per;
            if (cy == 0.f)      per = mNT[qq + 1] / fmaxf(1.f, cx);
            else if (cx == 0.f) per = mNR[qq + 1] / fmaxf(1.f, cy);
            else                per = 0.5f * (sxy / fmaxf(1.f, cy) + syx / fmaxf(1.f, cx));
            nzsum += per;
        }
        g_batch[b][0] = nzsum;
        g_batch[b][1] = mNR[0] / fmaxf(1.f, (float)(offY[1] - offY[0]));
        g_btick[b] = 0;                   // reset for next graph replay
    }

    // ---- Level 2: global completion (64 contenders) ----
    __syncthreads();
    __threadfence();
    if (tid == 0) fl2 = (atomicAdd(&g_ticket, 1) == BATCH - 1);
    __syncthreads();
    if (!fl2) return;

    __threadfence();                      // acquire all g_batch
    if (tid < BATCH) {
        sBnz[tid] = g_batch[tid][0];
        sBzz[tid] = g_batch[tid][1];
    }
    __syncthreads();
    if (tid == 0) {
        float a = 0.f, c = 0.f;
        for (int i = 0; i < BATCH; i++) { a += sBnz[i]; c += sBzz[i]; }
        out[0] = a / (float)BATCH;
        if (out_size > 1) out[1] = c / (float)BATCH;
        g_ticket = 0;                     // reset for next graph replay
    }
}

extern "C" void kernel_launch(void* const* d_in, const int* in_sizes, int n_in,
                              void* d_out, int out_size)
{
    const float4* target = (const float4*)d_in[0];
    const float4* reco   = (const float4*)d_in[1];
    const int*    ipid   = (const int*)d_in[2];
    const int*    opid   = (const int*)d_in[3];
    float*        out    = (float*)d_out;
    (void)in_sizes; (void)n_in;

    chamfer_fused<<<GRID, BLK>>>(target, reco, ipid, opid, out, out_size);
}